// round 1
// baseline (speedup 1.0000x reference)
#include <cuda_runtime.h>
#include <cstdint>

#define RADIUS 5
#define RS 11           // region size
#define EMB 128
#define BB 32
#define LL 512
#define NPOS (BB * LL)  // 16384

// 0 -> seq stored as int32, 1 -> seq stored as int64 (read low word at idx*2)
__device__ int g_seq_shift;

// Detect int32 vs int64 storage of seq. Tokens are uniform in [0,50000):
// for int64 little-endian layout, every odd 32-bit word is 0; for int32
// layout the odd words are real tokens and are (essentially) never all zero.
__global__ void detect_dtype_kernel(const int* __restrict__ seq32) {
    if (threadIdx.x == 0 && blockIdx.x == 0) {
        int any = 0;
#pragma unroll
        for (int i = 1; i < 256; i += 2) any |= seq32[i];
        g_seq_shift = (any == 0) ? 1 : 0;
    }
}

__global__ __launch_bounds__(256) void region_encoder_kernel(
    const int* __restrict__ seq32,
    const float* __restrict__ W,
    const float* __restrict__ U,
    float* __restrict__ out)
{
    const int warp = (blockIdx.x * blockDim.x + threadIdx.x) >> 5;
    const int lane = threadIdx.x & 31;
    if (warp >= NPOS) return;

    const int b = warp >> 9;          // / LL
    const int l = warp & (LL - 1);    // % LL
    const int shift = g_seq_shift;

    // lanes 0..10 load the window tokens seq[b, l-5+lane]; OOB -> 0 (padding)
    int tok = 0;
    const int p = l - RADIUS + lane;
    if (lane < RS && (unsigned)p < (unsigned)LL) {
        tok = seq32[(b * LL + p) << shift];
    }

    const int center = __shfl_sync(0xffffffffu, tok, RADIUS);

    // W row: 128 f32 = 32 float4; lane owns elements [4*lane, 4*lane+4)
    const float4 w = reinterpret_cast<const float4*>(W + (size_t)center * EMB)[lane];

    float4 acc = make_float4(-INFINITY, -INFINITY, -INFINITY, -INFINITY);

#pragma unroll
    for (int j = 0; j < RS; j++) {
        const int tj = __shfl_sync(0xffffffffu, tok, j);
        const size_t row = (size_t)tj * RS + (size_t)j;
        const float4 u = reinterpret_cast<const float4*>(U + row * EMB)[lane];
        acc.x = fmaxf(acc.x, u.x * w.x);
        acc.y = fmaxf(acc.y, u.y * w.y);
        acc.z = fmaxf(acc.z, u.z * w.z);
        acc.w = fmaxf(acc.w, u.w * w.w);
    }

    const float m = (center != 0) ? 1.0f : 0.0f;
    acc.x *= m; acc.y *= m; acc.z *= m; acc.w *= m;

    reinterpret_cast<float4*>(out + (size_t)warp * EMB)[lane] = acc;
}

extern "C" void kernel_launch(void* const* d_in, const int* in_sizes, int n_in,
                              void* d_out, int out_size) {
    const int*   seq32 = (const int*)d_in[0];
    const float* W     = (const float*)d_in[1];
    const float* U     = (const float*)d_in[2];
    float*       out   = (float*)d_out;

    detect_dtype_kernel<<<1, 32>>>(seq32);

    const int threads = 256;                 // 8 warps/block
    const int blocks  = NPOS / (threads / 32); // 2048
    region_encoder_kernel<<<blocks, threads>>>(seq32, W, U, out);
}